// round 9
// baseline (speedup 1.0000x reference)
#include <cuda_runtime.h>
#include <cuda_bf16.h>
#include <cuda_fp16.h>

#define N_NODES 50000
#define NEDGE   800000
#define ETOT    850000
#define C       128
#define H       8
#define NEG_SLOPE 0.2f
#define GEMM_BLOCKS 1563     // ceil(50000/32)
#define HIST_BLOCKS 1563     // ceil(800000/512), 4 edges/thread @128 threads

// ---------------- scratch (zero-initialized at module load) ----------------
__device__ __align__(16) __half g_h16[N_NODES * C];   // projected features, fp16
__device__ __align__(16) float g_acc[N_NODES * C];
__device__ float g_asrc[N_NODES * H];
__device__ float g_adst[N_NODES * H];
__device__ int   g_deg[N_NODES];
__device__ int   g_off[N_NODES];
__device__ int   g_cursor[N_NODES];
__device__ int   g_csrc[ETOT];
__device__ int   g_ecounter;
__device__ float g_colsum[C];
__device__ float g_colsq[C];

// ---------------- f32x2 helpers ----------------
__device__ __forceinline__ unsigned long long pack2(float lo, float hi) {
    unsigned long long r;
    asm("mov.b64 %0, {%1, %2};" : "=l"(r) : "f"(lo), "f"(hi));
    return r;
}
__device__ __forceinline__ void ffma2(unsigned long long& d,
                                      unsigned long long a, unsigned long long b) {
    asm("fma.rn.f32x2 %0, %1, %2, %0;" : "+l"(d) : "l"(a), "l"(b));
}
__device__ __forceinline__ float2 unpack2(unsigned long long v) {
    float2 f;
    asm("mov.b64 {%0, %1}, %2;" : "=f"(f.x), "=f"(f.y) : "l"(v));
    return f;
}

// ---------------- K1: fused [GEMM 8n x 4c register-blocked] | [degree histogram] ----------------
__global__ void k_gemm_hist(const float* __restrict__ x, const float* __restrict__ W,
                            const float* __restrict__ att_src, const float* __restrict__ att_dst,
                            const int* __restrict__ ei) {
    __shared__ unsigned long long xsd[32][C];   // 32KB: x dup'd as (v,v)
    int tid = threadIdx.x;

    if (blockIdx.x >= GEMM_BLOCKS) {
        int base = (blockIdx.x - GEMM_BLOCKS) * 512 + tid;
        #pragma unroll
        for (int r = 0; r < 4; r++) {
            int eid = base + r * 128;
            if (eid < NEDGE) atomicAdd(&g_deg[ei[NEDGE + eid]], 1);
        }
        return;
    }

    int nbase = blockIdx.x * 32;
    for (int i = tid; i < 32 * 32; i += 128) {
        int node = i >> 5;
        int c4   = i & 31;
        int gn   = nbase + node;
        float4 v = (gn < N_NODES) ? ((const float4*)x)[gn * 32 + c4]
                                  : make_float4(0.f, 0.f, 0.f, 0.f);
        xsd[node][c4 * 4 + 0] = pack2(v.x, v.x);
        xsd[node][c4 * 4 + 1] = pack2(v.y, v.y);
        xsd[node][c4 * 4 + 2] = pack2(v.z, v.z);
        xsd[node][c4 * 4 + 3] = pack2(v.w, v.w);
    }
    __syncthreads();

    int cg = tid & 31;
    int wp = tid >> 5;
    const unsigned long long* xr = xsd[wp * 8];

    unsigned long long acc[8][2];
    #pragma unroll
    for (int j = 0; j < 8; j++) { acc[j][0] = 0ull; acc[j][1] = 0ull; }

    const ulonglong2* W2 = (const ulonglong2*)W;

    #pragma unroll 2
    for (int k = 0; k < C; k++) {
        ulonglong2 w = W2[k * 32 + cg];
        #pragma unroll
        for (int j = 0; j < 8; j++) {
            unsigned long long xv = xr[j * C + k];
            ffma2(acc[j][0], w.x, xv);
            ffma2(acc[j][1], w.y, xv);
        }
    }

    float4 as = ((const float4*)att_src)[cg];
    float4 ad = ((const float4*)att_dst)[cg];

    #pragma unroll
    for (int j = 0; j < 8; j++) {
        float2 lo = unpack2(acc[j][0]);
        float2 hi = unpack2(acc[j][1]);
        float4 a = make_float4(lo.x, lo.y, hi.x, hi.y);
        float ps = a.x*as.x + a.y*as.y + a.z*as.z + a.w*as.w;
        float pd = a.x*ad.x + a.y*ad.y + a.z*ad.z + a.w*ad.w;
        ps += __shfl_xor_sync(0xffffffffu, ps, 1);
        ps += __shfl_xor_sync(0xffffffffu, ps, 2);
        pd += __shfl_xor_sync(0xffffffffu, pd, 1);
        pd += __shfl_xor_sync(0xffffffffu, pd, 2);
        int n = nbase + wp * 8 + j;
        if (n < N_NODES) {
            __half2 h01 = __floats2half2_rn(a.x, a.y);
            __half2 h23 = __floats2half2_rn(a.z, a.w);
            uint2 u;
            u.x = *(unsigned int*)&h01;
            u.y = *(unsigned int*)&h23;
            ((uint2*)g_h16)[n * 32 + cg] = u;
            if ((cg & 3) == 0) {
                int hd = cg >> 2;
                g_asrc[n * H + hd] = ps;
                g_adst[n * H + hd] = pd;
            }
        }
    }
}

// ---------------- K2: offsets (warp scan + 1 atomic/warp) + self-loop placement ----------------
__global__ void k_offsets() {
    int i    = blockIdx.x * 256 + threadIdx.x;
    int lane = threadIdx.x & 31;
    int v = (i < N_NODES) ? (g_deg[i] + 1) : 0;
    int incl = v;
    #pragma unroll
    for (int o = 1; o < 32; o <<= 1) {
        int t = __shfl_up_sync(0xffffffffu, incl, o);
        if (lane >= o) incl += t;
    }
    int total = __shfl_sync(0xffffffffu, incl, 31);
    int wbase = 0;
    if (lane == 0) wbase = atomicAdd(&g_ecounter, total);
    wbase = __shfl_sync(0xffffffffu, wbase, 0);
    if (i < N_NODES) {
        int o = wbase + incl - v;
        g_off[i]    = o;
        g_csrc[o]   = i;
        g_cursor[i] = o + 1;
    }
}

// ---------------- K3: fill CSR with real edges ----------------
__global__ void k_fill(const int* __restrict__ ei) {
    int eid = blockIdx.x * 256 + threadIdx.x;
    if (eid >= NEDGE) return;
    int s = ei[eid];
    int d = ei[NEDGE + eid];
    int pos = atomicAdd(&g_cursor[d], 1);
    g_csrc[pos] = s;
}

// ---------------- K4: half-warp-per-edge softmax-aggregate + fused BN stats ----------------
// Warp handles one dst node. Lanes 0-15 = half 0, lanes 16-31 = half 1.
// Lane covers 8 columns (hl*8..hl*8+7) via one uint4 (8 fp16) load per edge.
// ALL __shfl_sync calls are executed by ALL 32 lanes (uniform trip counts).
__global__ void k_aggregate() {
    __shared__ float ssum[C];
    __shared__ float ssq[C];
    int t = threadIdx.x;
    if (t < C) ssum[t] = 0.f; else ssq[t - C] = 0.f;
    __syncthreads();

    int warp = blockIdx.x * 8 + (t >> 5);
    int lane = t & 31;
    int half = lane >> 4;     // 0 or 1
    int hl   = lane & 15;     // column group: cols hl*8..hl*8+7
    int hd   = hl >> 1;       // head (2 lanes per head per half-warp)

    if (warp < N_NODES) {
        int beg = g_off[warp];
        int end = beg + g_deg[warp] + 1;
        int segn = end - beg;
        float adst = g_adst[warp * H + hd];
        const uint4* h16 = (const uint4*)g_h16;   // node row = 16 uint4

        float den = 0.f;
        float acc[8];
        #pragma unroll
        for (int k = 0; k < 8; k++) acc[k] = 0.f;

        for (int bp = 0; bp < segn; bp += 32) {
            int myp = beg + bp + lane;
            int sv = (myp < end) ? g_csrc[myp] : 0;     // coalesced segment load
            int cnt = min(32, segn - bp);
            int j = 0;
            // uniform main loop: 4 edges per iteration; half0 takes j,j+2; half1 takes j+1,j+3
            for (; j + 4 <= cnt; j += 4) {
                int s0 = __shfl_sync(0xffffffffu, sv, j + half);
                int s1 = __shfl_sync(0xffffffffu, sv, j + 2 + half);
                float e0 = g_asrc[s0 * H + hd];
                float e1 = g_asrc[s1 * H + hd];
                uint4 u0 = h16[s0 * 16 + hl];
                uint4 u1 = h16[s1 * 16 + hl];
                e0 += adst; e1 += adst;
                e0 = (e0 > 0.f) ? e0 : NEG_SLOPE * e0;
                e1 = (e1 > 0.f) ? e1 : NEG_SLOPE * e1;
                float x0 = __expf(e0);
                float x1 = __expf(e1);
                den += x0 + x1;
                float2 a0 = __half22float2(*(__half2*)&u0.x);
                float2 b0 = __half22float2(*(__half2*)&u0.y);
                float2 c0 = __half22float2(*(__half2*)&u0.z);
                float2 d0 = __half22float2(*(__half2*)&u0.w);
                acc[0] += x0 * a0.x; acc[1] += x0 * a0.y;
                acc[2] += x0 * b0.x; acc[3] += x0 * b0.y;
                acc[4] += x0 * c0.x; acc[5] += x0 * c0.y;
                acc[6] += x0 * d0.x; acc[7] += x0 * d0.y;
                float2 a1 = __half22float2(*(__half2*)&u1.x);
                float2 b1 = __half22float2(*(__half2*)&u1.y);
                float2 c1 = __half22float2(*(__half2*)&u1.z);
                float2 d1 = __half22float2(*(__half2*)&u1.w);
                acc[0] += x1 * a1.x; acc[1] += x1 * a1.y;
                acc[2] += x1 * b1.x; acc[3] += x1 * b1.y;
                acc[4] += x1 * c1.x; acc[5] += x1 * c1.y;
                acc[6] += x1 * d1.x; acc[7] += x1 * d1.y;
            }
            // uniform remainder: shfl by all lanes; only matching-parity half accumulates
            for (; j < cnt; j++) {
                int s = __shfl_sync(0xffffffffu, sv, j);
                if ((j & 1) == half) {
                    float e = g_asrc[s * H + hd] + adst;
                    e = (e > 0.f) ? e : NEG_SLOPE * e;
                    float ex = __expf(e);
                    den += ex;
                    uint4 u = h16[s * 16 + hl];
                    float2 a = __half22float2(*(__half2*)&u.x);
                    float2 b = __half22float2(*(__half2*)&u.y);
                    float2 c = __half22float2(*(__half2*)&u.z);
                    float2 d = __half22float2(*(__half2*)&u.w);
                    acc[0] += ex * a.x; acc[1] += ex * a.y;
                    acc[2] += ex * b.x; acc[3] += ex * b.y;
                    acc[4] += ex * c.x; acc[5] += ex * c.y;
                    acc[6] += ex * d.x; acc[7] += ex * d.y;
                }
            }
        }

        // combine the two half-warps (same columns, disjoint edge sets)
        den += __shfl_xor_sync(0xffffffffu, den, 16);
        #pragma unroll
        for (int k = 0; k < 8; k++)
            acc[k] += __shfl_xor_sync(0xffffffffu, acc[k], 16);

        float inv = 1.f / (den + 1e-16f);
        #pragma unroll
        for (int k = 0; k < 8; k++) acc[k] *= inv;

        if (half == 0) {
            float4* orow = (float4*)(g_acc + warp * C);
            orow[hl * 2 + 0] = make_float4(acc[0], acc[1], acc[2], acc[3]);
            orow[hl * 2 + 1] = make_float4(acc[4], acc[5], acc[6], acc[7]);
            int c = hl * 8;
            #pragma unroll
            for (int k = 0; k < 8; k++) {
                atomicAdd(&ssum[c + k], acc[k]);
                atomicAdd(&ssq[c + k], acc[k] * acc[k]);
            }
        }
    }
    __syncthreads();
    if (t < C) {
        atomicAdd(&g_colsum[t], ssum[t]);
        atomicAdd(&g_colsq[t], ssq[t]);
    }
}

// ---------------- K5: normalize + ReLU (+ deg reset; deg is dead after K4) ----------------
__global__ void k_final(const float* __restrict__ gamma, const float* __restrict__ beta,
                        float* __restrict__ out) {
    __shared__ float sscale[C];
    __shared__ float sshift[C];
    int t = threadIdx.x;
    if (t < C) {
        float inv_n = 1.f / (float)N_NODES;
        float mean = g_colsum[t] * inv_n;
        float var  = g_colsq[t] * inv_n - mean * mean;
        float sc   = gamma[t] * rsqrtf(var + 1e-5f);
        sscale[t] = sc;
        sshift[t] = beta[t] - mean * sc;
    }
    __syncthreads();
    int v4 = blockIdx.x * 256 + t;
    if (v4 < N_NODES) g_deg[v4] = 0;          // cleanup for next invocation
    if (v4 < N_NODES * 32) {
        int cb = (v4 & 31) * 4;
        float4 a = ((const float4*)g_acc)[v4];
        float4 r;
        r.x = fmaxf(a.x * sscale[cb + 0] + sshift[cb + 0], 0.f);
        r.y = fmaxf(a.y * sscale[cb + 1] + sshift[cb + 1], 0.f);
        r.z = fmaxf(a.z * sscale[cb + 2] + sshift[cb + 2], 0.f);
        r.w = fmaxf(a.w * sscale[cb + 3] + sshift[cb + 3], 0.f);
        ((float4*)out)[v4] = r;
    }
}

// ---------------- K6: tiny cleanup ----------------
__global__ void k_cleanup() {
    int t = threadIdx.x;
    if (t < C) { g_colsum[t] = 0.f; g_colsq[t] = 0.f; }
    if (t == 0) g_ecounter = 0;
}

// ---------------- launch ----------------
extern "C" void kernel_launch(void* const* d_in, const int* in_sizes, int n_in,
                              void* d_out, int out_size) {
    const float* x       = (const float*)d_in[0];
    const int*   ei      = (const int*)d_in[1];
    const float* W       = (const float*)d_in[2];
    const float* att_src = (const float*)d_in[3];
    const float* att_dst = (const float*)d_in[4];
    const float* gamma   = (const float*)d_in[6];
    const float* beta    = (const float*)d_in[7];
    float*       out     = (float*)d_out;

    k_gemm_hist<<<GEMM_BLOCKS + HIST_BLOCKS, 128>>>(x, W, att_src, att_dst, ei);
    k_offsets<<<(N_NODES + 255) / 256, 256>>>();
    k_fill<<<(NEDGE + 255) / 256, 256>>>(ei);
    k_aggregate<<<(N_NODES + 7) / 8, 256>>>();            // profiled launch (index 3)
    k_final<<<(N_NODES * 32 + 255) / 256, 256>>>(gamma, beta, out);
    k_cleanup<<<1, 256>>>();
}

// round 10
// speedup vs baseline: 1.1848x; 1.1848x over previous
#include <cuda_runtime.h>
#include <cuda_bf16.h>
#include <cuda_fp16.h>

#define N_NODES 50000
#define NEDGE   800000
#define ETOT    850000
#define C       128
#define H       8
#define NEG_SLOPE 0.2f
#define GEMM_BLOCKS 1563     // ceil(50000/32)
#define HIST_BLOCKS 1563     // ceil(800000/512), 4 edges/thread @128 threads

// ---------------- scratch (zero-initialized at module load) ----------------
__device__ __align__(16) __half g_h16[N_NODES * C];   // projected features, fp16
__device__ __align__(16) float g_acc[N_NODES * C];
__device__ float g_asrc[N_NODES * H];
__device__ float g_adst[N_NODES * H];
__device__ int   g_deg[N_NODES];
__device__ int   g_off[N_NODES];
__device__ int   g_cursor[N_NODES];
__device__ int   g_csrc[ETOT];
__device__ int   g_ecounter;
__device__ float g_colsum[C];
__device__ float g_colsq[C];

// ---------------- f32x2 helpers ----------------
__device__ __forceinline__ unsigned long long pack2(float lo, float hi) {
    unsigned long long r;
    asm("mov.b64 %0, {%1, %2};" : "=l"(r) : "f"(lo), "f"(hi));
    return r;
}
__device__ __forceinline__ void ffma2(unsigned long long& d,
                                      unsigned long long a, unsigned long long b) {
    asm("fma.rn.f32x2 %0, %1, %2, %0;" : "+l"(d) : "l"(a), "l"(b));
}
__device__ __forceinline__ float2 unpack2(unsigned long long v) {
    float2 f;
    asm("mov.b64 {%0, %1}, %2;" : "=f"(f.x), "=f"(f.y) : "l"(v));
    return f;
}

// ---------------- K0a/K0b/K0c: front-of-call zeroing (also shifts gemm to profile slot 3) ----------------
__global__ void k_zero_deg() {
    int i = blockIdx.x * 256 + threadIdx.x;
    if (i < N_NODES) g_deg[i] = 0;
}
__global__ void k_zero_stats() {
    int t = threadIdx.x;
    if (t < C) { g_colsum[t] = 0.f; g_colsq[t] = 0.f; }
}
__global__ void k_zero_ctr() {
    g_ecounter = 0;
}

// ---------------- K1: fused [GEMM 8n x 4c, 2-k LDS.128 inner] | [degree histogram] ----------------
__global__ void k_gemm_hist(const float* __restrict__ x, const float* __restrict__ W,
                            const float* __restrict__ att_src, const float* __restrict__ att_dst,
                            const int* __restrict__ ei) {
    __shared__ unsigned long long xsd[32][C];   // 32KB: x dup'd as (v,v)
    int tid = threadIdx.x;

    if (blockIdx.x >= GEMM_BLOCKS) {
        int base = (blockIdx.x - GEMM_BLOCKS) * 512 + tid;
        #pragma unroll
        for (int r = 0; r < 4; r++) {
            int eid = base + r * 128;
            if (eid < NEDGE) atomicAdd(&g_deg[ei[NEDGE + eid]], 1);
        }
        return;
    }

    int nbase = blockIdx.x * 32;
    for (int i = tid; i < 32 * 32; i += 128) {
        int node = i >> 5;
        int c4   = i & 31;
        int gn   = nbase + node;
        float4 v = (gn < N_NODES) ? ((const float4*)x)[gn * 32 + c4]
                                  : make_float4(0.f, 0.f, 0.f, 0.f);
        xsd[node][c4 * 4 + 0] = pack2(v.x, v.x);
        xsd[node][c4 * 4 + 1] = pack2(v.y, v.y);
        xsd[node][c4 * 4 + 2] = pack2(v.z, v.z);
        xsd[node][c4 * 4 + 3] = pack2(v.w, v.w);
    }
    __syncthreads();

    int cg = tid & 31;
    int wp = tid >> 5;
    const unsigned long long* xr = xsd[wp * 8];

    unsigned long long acc[8][2];
    #pragma unroll
    for (int j = 0; j < 8; j++) { acc[j][0] = 0ull; acc[j][1] = 0ull; }

    const ulonglong2* W2 = (const ulonglong2*)W;

    #pragma unroll 2
    for (int k = 0; k < C; k += 2) {
        ulonglong2 w0 = W2[k * 32 + cg];
        ulonglong2 w1 = W2[(k + 1) * 32 + cg];
        #pragma unroll
        for (int j = 0; j < 8; j++) {
            ulonglong2 xv = *(const ulonglong2*)&xr[j * C + k];  // 2 k-values, one LDS.128
            ffma2(acc[j][0], w0.x, xv.x);
            ffma2(acc[j][1], w0.y, xv.x);
            ffma2(acc[j][0], w1.x, xv.y);
            ffma2(acc[j][1], w1.y, xv.y);
        }
    }

    float4 as = ((const float4*)att_src)[cg];
    float4 ad = ((const float4*)att_dst)[cg];

    #pragma unroll
    for (int j = 0; j < 8; j++) {
        float2 lo = unpack2(acc[j][0]);
        float2 hi = unpack2(acc[j][1]);
        float4 a = make_float4(lo.x, lo.y, hi.x, hi.y);
        float ps = a.x*as.x + a.y*as.y + a.z*as.z + a.w*as.w;
        float pd = a.x*ad.x + a.y*ad.y + a.z*ad.z + a.w*ad.w;
        ps += __shfl_xor_sync(0xffffffffu, ps, 1);
        ps += __shfl_xor_sync(0xffffffffu, ps, 2);
        pd += __shfl_xor_sync(0xffffffffu, pd, 1);
        pd += __shfl_xor_sync(0xffffffffu, pd, 2);
        int n = nbase + wp * 8 + j;
        if (n < N_NODES) {
            __half2 h01 = __floats2half2_rn(a.x, a.y);
            __half2 h23 = __floats2half2_rn(a.z, a.w);
            uint2 u;
            u.x = *(unsigned int*)&h01;
            u.y = *(unsigned int*)&h23;
            ((uint2*)g_h16)[n * 32 + cg] = u;
            if ((cg & 3) == 0) {
                int hd = cg >> 2;
                g_asrc[n * H + hd] = ps;
                g_adst[n * H + hd] = pd;
            }
        }
    }
}

// ---------------- K2: offsets (warp scan + 1 atomic/warp) + self-loop placement ----------------
__global__ void k_offsets() {
    int i    = blockIdx.x * 256 + threadIdx.x;
    int lane = threadIdx.x & 31;
    int v = (i < N_NODES) ? (g_deg[i] + 1) : 0;
    int incl = v;
    #pragma unroll
    for (int o = 1; o < 32; o <<= 1) {
        int t = __shfl_up_sync(0xffffffffu, incl, o);
        if (lane >= o) incl += t;
    }
    int total = __shfl_sync(0xffffffffu, incl, 31);
    int wbase = 0;
    if (lane == 0) wbase = atomicAdd(&g_ecounter, total);
    wbase = __shfl_sync(0xffffffffu, wbase, 0);
    if (i < N_NODES) {
        int o = wbase + incl - v;
        g_off[i]    = o;
        g_csrc[o]   = i;
        g_cursor[i] = o + 1;
    }
}

// ---------------- K3: fill CSR with real edges ----------------
__global__ void k_fill(const int* __restrict__ ei) {
    int eid = blockIdx.x * 256 + threadIdx.x;
    if (eid >= NEDGE) return;
    int s = ei[eid];
    int d = ei[NEDGE + eid];
    int pos = atomicAdd(&g_cursor[d], 1);
    g_csrc[pos] = s;
}

// ---------------- K4: warp-per-dst single-pass softmax-aggregate + fused BN stats (R7 version) ----------------
__global__ void k_aggregate() {
    __shared__ float ssum[C];
    __shared__ float ssq[C];
    int t = threadIdx.x;
    if (t < C) ssum[t] = 0.f; else ssq[t - C] = 0.f;
    __syncthreads();

    int warp = blockIdx.x * 8 + (t >> 5);
    int lane = t & 31;
    int hd   = lane >> 2;

    if (warp < N_NODES) {
        int beg = g_off[warp];
        int end = beg + g_deg[warp] + 1;
        float adst = g_adst[warp * H + hd];
        const uint2* h16 = (const uint2*)g_h16;

        float den = 0.f;
        float4 acc = make_float4(0.f, 0.f, 0.f, 0.f);

        for (int bp = beg; bp < end; bp += 32) {
            int myp = bp + lane;
            int sv = (myp < end) ? g_csrc[myp] : 0;
            int cnt = min(32, end - bp);
            int j = 0;
            for (; j + 4 <= cnt; j += 4) {
                int s0 = __shfl_sync(0xffffffffu, sv, j);
                int s1 = __shfl_sync(0xffffffffu, sv, j + 1);
                int s2 = __shfl_sync(0xffffffffu, sv, j + 2);
                int s3 = __shfl_sync(0xffffffffu, sv, j + 3);
                float e0 = g_asrc[s0 * H + hd];
                float e1 = g_asrc[s1 * H + hd];
                float e2 = g_asrc[s2 * H + hd];
                float e3 = g_asrc[s3 * H + hd];
                uint2 u0 = h16[s0 * 32 + lane];
                uint2 u1 = h16[s1 * 32 + lane];
                uint2 u2 = h16[s2 * 32 + lane];
                uint2 u3 = h16[s3 * 32 + lane];
                e0 += adst; e1 += adst; e2 += adst; e3 += adst;
                e0 = (e0 > 0.f) ? e0 : NEG_SLOPE * e0;
                e1 = (e1 > 0.f) ? e1 : NEG_SLOPE * e1;
                e2 = (e2 > 0.f) ? e2 : NEG_SLOPE * e2;
                e3 = (e3 > 0.f) ? e3 : NEG_SLOPE * e3;
                float x0 = __expf(e0), x1 = __expf(e1);
                float x2 = __expf(e2), x3 = __expf(e3);
                den += (x0 + x1) + (x2 + x3);
                float2 l0 = __half22float2(*(__half2*)&u0.x), m0 = __half22float2(*(__half2*)&u0.y);
                float2 l1 = __half22float2(*(__half2*)&u1.x), m1 = __half22float2(*(__half2*)&u1.y);
                float2 l2 = __half22float2(*(__half2*)&u2.x), m2 = __half22float2(*(__half2*)&u2.y);
                float2 l3 = __half22float2(*(__half2*)&u3.x), m3 = __half22float2(*(__half2*)&u3.y);
                acc.x += x0 * l0.x; acc.y += x0 * l0.y; acc.z += x0 * m0.x; acc.w += x0 * m0.y;
                acc.x += x1 * l1.x; acc.y += x1 * l1.y; acc.z += x1 * m1.x; acc.w += x1 * m1.y;
                acc.x += x2 * l2.x; acc.y += x2 * l2.y; acc.z += x2 * m2.x; acc.w += x2 * m2.y;
                acc.x += x3 * l3.x; acc.y += x3 * l3.y; acc.z += x3 * m3.x; acc.w += x3 * m3.y;
            }
            for (; j < cnt; j++) {
                int s = __shfl_sync(0xffffffffu, sv, j);
                float e = g_asrc[s * H + hd] + adst;
                e = (e > 0.f) ? e : NEG_SLOPE * e;
                float ex = __expf(e);
                den += ex;
                uint2 u = h16[s * 32 + lane];
                float2 lo = __half22float2(*(__half2*)&u.x);
                float2 hi = __half22float2(*(__half2*)&u.y);
                acc.x += ex * lo.x; acc.y += ex * lo.y;
                acc.z += ex * hi.x; acc.w += ex * hi.y;
            }
        }

        float inv = 1.f / (den + 1e-16f);
        acc.x *= inv; acc.y *= inv; acc.z *= inv; acc.w *= inv;
        ((float4*)g_acc)[warp * 32 + lane] = acc;

        int c = lane * 4;
        atomicAdd(&ssum[c + 0], acc.x); atomicAdd(&ssq[c + 0], acc.x * acc.x);
        atomicAdd(&ssum[c + 1], acc.y); atomicAdd(&ssq[c + 1], acc.y * acc.y);
        atomicAdd(&ssum[c + 2], acc.z); atomicAdd(&ssq[c + 2], acc.z * acc.z);
        atomicAdd(&ssum[c + 3], acc.w); atomicAdd(&ssq[c + 3], acc.w * acc.w);
    }
    __syncthreads();
    if (t < C) {
        atomicAdd(&g_colsum[t], ssum[t]);
        atomicAdd(&g_colsq[t], ssq[t]);
    }
}

// ---------------- K5: normalize + ReLU ----------------
__global__ void k_final(const float* __restrict__ gamma, const float* __restrict__ beta,
                        float* __restrict__ out) {
    __shared__ float sscale[C];
    __shared__ float sshift[C];
    int t = threadIdx.x;
    if (t < C) {
        float inv_n = 1.f / (float)N_NODES;
        float mean = g_colsum[t] * inv_n;
        float var  = g_colsq[t] * inv_n - mean * mean;
        float sc   = gamma[t] * rsqrtf(var + 1e-5f);
        sscale[t] = sc;
        sshift[t] = beta[t] - mean * sc;
    }
    __syncthreads();
    int v4 = blockIdx.x * 256 + t;
    if (v4 < N_NODES * 32) {
        int cb = (v4 & 31) * 4;
        float4 a = ((const float4*)g_acc)[v4];
        float4 r;
        r.x = fmaxf(a.x * sscale[cb + 0] + sshift[cb + 0], 0.f);
        r.y = fmaxf(a.y * sscale[cb + 1] + sshift[cb + 1], 0.f);
        r.z = fmaxf(a.z * sscale[cb + 2] + sshift[cb + 2], 0.f);
        r.w = fmaxf(a.w * sscale[cb + 3] + sshift[cb + 3], 0.f);
        ((float4*)out)[v4] = r;
    }
}

// ---------------- launch ----------------
extern "C" void kernel_launch(void* const* d_in, const int* in_sizes, int n_in,
                              void* d_out, int out_size) {
    const float* x       = (const float*)d_in[0];
    const int*   ei      = (const int*)d_in[1];
    const float* W       = (const float*)d_in[2];
    const float* att_src = (const float*)d_in[3];
    const float* att_dst = (const float*)d_in[4];
    const float* gamma   = (const float*)d_in[6];
    const float* beta    = (const float*)d_in[7];
    float*       out     = (float*)d_out;

    k_zero_deg<<<(N_NODES + 255) / 256, 256>>>();
    k_zero_stats<<<1, 128>>>();
    k_zero_ctr<<<1, 1>>>();
    k_gemm_hist<<<GEMM_BLOCKS + HIST_BLOCKS, 128>>>(x, W, att_src, att_dst, ei);  // profiled (index 3)
    k_offsets<<<(N_NODES + 255) / 256, 256>>>();
    k_fill<<<(NEDGE + 255) / 256, 256>>>(ei);
    k_aggregate<<<(N_NODES + 7) / 8, 256>>>();
    k_final<<<(N_NODES * 32 + 255) / 256, 256>>>(gamma, beta, out);
}

// round 11
// speedup vs baseline: 1.4497x; 1.2235x over previous
#include <cuda_runtime.h>
#include <cuda_fp16.h>
#include <mma.h>
using namespace nvcuda;

#define N_NODES 50000
#define NEDGE   800000
#define ETOT    850000
#define C       128
#define H       8
#define NEG_SLOPE 0.2f
#define MTILE   128
#define GEMM_BLOCKS 391      // ceil(50000/128)
#define HIST_BLOCKS 782      // ceil(800000/1024), 4 edges/thread @256 threads
#define LDH     144          // half ldm for sA/sB (288B rows: 32B-aligned)
#define LDF     136          // float ldm for epilogue scratch (544B rows: 32B-aligned)
#define SMEM_DYN (2 * 128 * LDH * sizeof(__half))   // 73728 B

// ---------------- scratch (zero-initialized at module load) ----------------
__device__ __align__(16) __half g_h16[N_NODES * C];   // projected features, fp16
__device__ __align__(16) float g_acc[N_NODES * C];
__device__ float g_asrc[N_NODES * H];
__device__ float g_adst[N_NODES * H];
__device__ int   g_deg[N_NODES];
__device__ int   g_off[N_NODES];
__device__ int   g_cursor[N_NODES];
__device__ int   g_csrc[ETOT];
__device__ int   g_ecounter;
__device__ float g_colsum[C];
__device__ float g_colsq[C];

// ---------------- K0a/K0b/K0c: front-of-call zeroing (keeps gemm at profile slot 3) ----------------
__global__ void k_zero_deg() {
    int i = blockIdx.x * 256 + threadIdx.x;
    if (i < N_NODES) g_deg[i] = 0;
}
__global__ void k_zero_stats() {
    int t = threadIdx.x;
    if (t < C) { g_colsum[t] = 0.f; g_colsq[t] = 0.f; }
}
__global__ void k_zero_ctr() {
    g_ecounter = 0;
}

// ---------------- K1: fused [tensor-core GEMM + attention epilogue] | [degree histogram] ----------------
__global__ void k_gemm_hist(const float* __restrict__ x, const float* __restrict__ W,
                            const float* __restrict__ att_src, const float* __restrict__ att_dst,
                            const int* __restrict__ ei) {
    extern __shared__ __align__(32) char smem_raw[];
    __half* sA = (__half*)smem_raw;        // x tile  [128][LDH]
    __half* sB = sA + 128 * LDH;           // W       [128][LDH]
    int tid = threadIdx.x;

    if (blockIdx.x >= GEMM_BLOCKS) {
        int base = (blockIdx.x - GEMM_BLOCKS) * 1024 + tid;
        #pragma unroll
        for (int r = 0; r < 4; r++) {
            int eid = base + r * 256;
            if (eid < NEDGE) atomicAdd(&g_deg[ei[NEDGE + eid]], 1);
        }
        return;
    }

    int nbase = blockIdx.x * MTILE;
    // stage x tile and W, converting f32 -> fp16
    for (int i = tid; i < 128 * 32; i += 256) {
        int row = i >> 5, c4 = i & 31;
        int gn = nbase + row;
        float4 v = (gn < N_NODES) ? ((const float4*)x)[gn * 32 + c4]
                                  : make_float4(0.f, 0.f, 0.f, 0.f);
        __half2 h0 = __floats2half2_rn(v.x, v.y);
        __half2 h1 = __floats2half2_rn(v.z, v.w);
        uint2 u; u.x = *(unsigned*)&h0; u.y = *(unsigned*)&h1;
        *((uint2*)(sA + row * LDH) + c4) = u;

        float4 wv = ((const float4*)W)[row * 32 + c4];
        __half2 w0 = __floats2half2_rn(wv.x, wv.y);
        __half2 w1 = __floats2half2_rn(wv.z, wv.w);
        uint2 uw; uw.x = *(unsigned*)&w0; uw.y = *(unsigned*)&w1;
        *((uint2*)(sB + row * LDH) + c4) = uw;
    }
    __syncthreads();

    int w = tid >> 5, lane = tid & 31;

    wmma::fragment<wmma::accumulator, 16, 16, 16, float> acc[8];
    #pragma unroll
    for (int nt = 0; nt < 8; nt++) wmma::fill_fragment(acc[nt], 0.f);

    #pragma unroll
    for (int ks = 0; ks < 8; ks++) {
        wmma::fragment<wmma::matrix_a, 16, 16, 16, __half, wmma::row_major> a;
        wmma::load_matrix_sync(a, sA + (w * 16) * LDH + ks * 16, LDH);
        #pragma unroll
        for (int nt = 0; nt < 8; nt++) {
            wmma::fragment<wmma::matrix_b, 16, 16, 16, __half, wmma::row_major> b;
            wmma::load_matrix_sync(b, sB + (ks * 16) * LDH + nt * 16, LDH);
            wmma::mma_sync(acc[nt], a, b, acc[nt]);
        }
    }
    __syncthreads();   // all warps done reading sA/sB; safe to reuse as scratch

    float* sc = (float*)smem_raw + w * (16 * LDF);   // per-warp 16x128 f32 scratch
    #pragma unroll
    for (int nt = 0; nt < 8; nt++)
        wmma::store_matrix_sync(sc + nt * 16, acc[nt], LDF, wmma::mem_row_major);
    __syncwarp();

    // epilogue: 2 lanes per row; lane covers 64 cols (4 heads)
    int r = lane >> 1, p = lane & 1;
    int n = nbase + w * 16 + r;
    if (n < N_NODES) {
        const float4* row4 = (const float4*)(sc + r * LDF) + p * 16;
        const float4* as4 = ((const float4*)att_src) + p * 16;
        const float4* ad4 = ((const float4*)att_dst) + p * 16;
        uint4* hout = ((uint4*)(g_h16 + n * C)) + p * 8;
        float ps[4] = {0.f, 0.f, 0.f, 0.f};
        float pd[4] = {0.f, 0.f, 0.f, 0.f};
        #pragma unroll
        for (int q = 0; q < 8; q++) {           // 8 cols per q; head changes every 2 q
            float4 v0 = row4[q * 2], v1 = row4[q * 2 + 1];
            float4 a0 = as4[q * 2], a1 = as4[q * 2 + 1];
            float4 b0 = ad4[q * 2], b1 = ad4[q * 2 + 1];
            int hh = q >> 1;
            ps[hh] += v0.x*a0.x + v0.y*a0.y + v0.z*a0.z + v0.w*a0.w
                    + v1.x*a1.x + v1.y*a1.y + v1.z*a1.z + v1.w*a1.w;
            pd[hh] += v0.x*b0.x + v0.y*b0.y + v0.z*b0.z + v0.w*b0.w
                    + v1.x*b1.x + v1.y*b1.y + v1.z*b1.z + v1.w*b1.w;
            __half2 q0 = __floats2half2_rn(v0.x, v0.y);
            __half2 q1 = __floats2half2_rn(v0.z, v0.w);
            __half2 q2 = __floats2half2_rn(v1.x, v1.y);
            __half2 q3 = __floats2half2_rn(v1.z, v1.w);
            uint4 u;
            u.x = *(unsigned*)&q0; u.y = *(unsigned*)&q1;
            u.z = *(unsigned*)&q2; u.w = *(unsigned*)&q3;
            hout[q] = u;
        }
        #pragma unroll
        for (int i2 = 0; i2 < 4; i2++) {
            g_asrc[n * H + p * 4 + i2] = ps[i2];
            g_adst[n * H + p * 4 + i2] = pd[i2];
        }
    }
}

// ---------------- K2: offsets (warp scan + 1 atomic/warp) + self-loop placement ----------------
__global__ void k_offsets() {
    int i    = blockIdx.x * 256 + threadIdx.x;
    int lane = threadIdx.x & 31;
    int v = (i < N_NODES) ? (g_deg[i] + 1) : 0;
    int incl = v;
    #pragma unroll
    for (int o = 1; o < 32; o <<= 1) {
        int t = __shfl_up_sync(0xffffffffu, incl, o);
        if (lane >= o) incl += t;
    }
    int total = __shfl_sync(0xffffffffu, incl, 31);
    int wbase = 0;
    if (lane == 0) wbase = atomicAdd(&g_ecounter, total);
    wbase = __shfl_sync(0xffffffffu, wbase, 0);
    if (i < N_NODES) {
        int o = wbase + incl - v;
        g_off[i]    = o;
        g_csrc[o]   = i;
        g_cursor[i] = o + 1;
    }
}

// ---------------- K3: fill CSR with real edges ----------------
__global__ void k_fill(const int* __restrict__ ei) {
    int eid = blockIdx.x * 256 + threadIdx.x;
    if (eid >= NEDGE) return;
    int s = ei[eid];
    int d = ei[NEDGE + eid];
    int pos = atomicAdd(&g_cursor[d], 1);
    g_csrc[pos] = s;
}

// ---------------- K4: warp-per-dst single-pass softmax-aggregate + fused BN stats ----------------
__global__ void k_aggregate() {
    __shared__ float ssum[C];
    __shared__ float ssq[C];
    int t = threadIdx.x;
    if (t < C) ssum[t] = 0.f; else ssq[t - C] = 0.f;
    __syncthreads();

    int warp = blockIdx.x * 8 + (t >> 5);
    int lane = t & 31;
    int hd   = lane >> 2;

    if (warp < N_NODES) {
        int beg = g_off[warp];
        int end = beg + g_deg[warp] + 1;
        float adst = g_adst[warp * H + hd];
        const uint2* h16 = (const uint2*)g_h16;

        float den = 0.f;
        float4 acc = make_float4(0.f, 0.f, 0.f, 0.f);

        for (int bp = beg; bp < end; bp += 32) {
            int myp = bp + lane;
            int sv = (myp < end) ? g_csrc[myp] : 0;
            int cnt = min(32, end - bp);
            int j = 0;
            for (; j + 4 <= cnt; j += 4) {
                int s0 = __shfl_sync(0xffffffffu, sv, j);
                int s1 = __shfl_sync(0xffffffffu, sv, j + 1);
                int s2 = __shfl_sync(0xffffffffu, sv, j + 2);
                int s3 = __shfl_sync(0xffffffffu, sv, j + 3);
                float e0 = g_asrc[s0 * H + hd];
                float e1 = g_asrc[s1 * H + hd];
                float e2 = g_asrc[s2 * H + hd];
                float e3 = g_asrc[s3 * H + hd];
                uint2 u0 = h16[s0 * 32 + lane];
                uint2 u1 = h16[s1 * 32 + lane];
                uint2 u2 = h16[s2 * 32 + lane];
                uint2 u3 = h16[s3 * 32 + lane];
                e0 += adst; e1 += adst; e2 += adst; e3 += adst;
                e0 = (e0 > 0.f) ? e0 : NEG_SLOPE * e0;
                e1 = (e1 > 0.f) ? e1 : NEG_SLOPE * e1;
                e2 = (e2 > 0.f) ? e2 : NEG_SLOPE * e2;
                e3 = (e3 > 0.f) ? e3 : NEG_SLOPE * e3;
                float x0 = __expf(e0), x1 = __expf(e1);
                float x2 = __expf(e2), x3 = __expf(e3);
                den += (x0 + x1) + (x2 + x3);
                float2 l0 = __half22float2(*(__half2*)&u0.x), m0 = __half22float2(*(__half2*)&u0.y);
                float2 l1 = __half22float2(*(__half2*)&u1.x), m1 = __half22float2(*(__half2*)&u1.y);
                float2 l2 = __half22float2(*(__half2*)&u2.x), m2 = __half22float2(*(__half2*)&u2.y);
                float2 l3 = __half22float2(*(__half2*)&u3.x), m3 = __half22float2(*(__half2*)&u3.y);
                acc.x += x0 * l0.x; acc.y += x0 * l0.y; acc.z += x0 * m0.x; acc.w += x0 * m0.y;
                acc.x += x1 * l1.x; acc.y += x1 * l1.y; acc.z += x1 * m1.x; acc.w += x1 * m1.y;
                acc.x += x2 * l2.x; acc.y += x2 * l2.y; acc.z += x2 * m2.x; acc.w += x2 * m2.y;
                acc.x += x3 * l3.x; acc.y += x3 * l3.y; acc.z += x3 * m3.x; acc.w += x3 * m3.y;
            }
            for (; j < cnt; j++) {
                int s = __shfl_sync(0xffffffffu, sv, j);
                float e = g_asrc[s * H + hd] + adst;
                e = (e > 0.f) ? e : NEG_SLOPE * e;
                float ex = __expf(e);
                den += ex;
                uint2 u = h16[s * 32 + lane];
                float2 lo = __half22float2(*(__half2*)&u.x);
                float2 hi = __half22float2(*(__half2*)&u.y);
                acc.x += ex * lo.x; acc.y += ex * lo.y;
                acc.z += ex * hi.x; acc.w += ex * hi.y;
            }
        }

        float inv = 1.f / (den + 1e-16f);
        acc.x *= inv; acc.y *= inv; acc.z *= inv; acc.w *= inv;
        ((float4*)g_acc)[warp * 32 + lane] = acc;

        int c = lane * 4;
        atomicAdd(&ssum[c + 0], acc.x); atomicAdd(&ssq[c + 0], acc.x * acc.x);
        atomicAdd(&ssum[c + 1], acc.y); atomicAdd(&ssq[c + 1], acc.y * acc.y);
        atomicAdd(&ssum[c + 2], acc.z); atomicAdd(&ssq[c + 2], acc.z * acc.z);
        atomicAdd(&ssum[c + 3], acc.w); atomicAdd(&ssq[c + 3], acc.w * acc.w);
    }
    __syncthreads();
    if (t < C) {
        atomicAdd(&g_colsum[t], ssum[t]);
        atomicAdd(&g_colsq[t], ssq[t]);
    }
}

// ---------------- K5: normalize + ReLU ----------------
__global__ void k_final(const float* __restrict__ gamma, const float* __restrict__ beta,
                        float* __restrict__ out) {
    __shared__ float sscale[C];
    __shared__ float sshift[C];
    int t = threadIdx.x;
    if (t < C) {
        float inv_n = 1.f / (float)N_NODES;
        float mean = g_colsum[t] * inv_n;
        float var  = g_colsq[t] * inv_n - mean * mean;
        float sc   = gamma[t] * rsqrtf(var + 1e-5f);
        sscale[t] = sc;
        sshift[t] = beta[t] - mean * sc;
    }
    __syncthreads();
    int v4 = blockIdx.x * 256 + t;
    if (v4 < N_NODES * 32) {
        int cb = (v4 & 31) * 4;
        float4 a = ((const float4*)g_acc)[v4];
        float4 r;
        r.x = fmaxf(a.x * sscale[cb + 0] + sshift[cb + 0], 0.f);
        r.y = fmaxf(a.y * sscale[cb + 1] + sshift[cb + 1], 0.f);
        r.z = fmaxf(a.z * sscale[cb + 2] + sshift[cb + 2], 0.f);
        r.w = fmaxf(a.w * sscale[cb + 3] + sshift[cb + 3], 0.f);
        ((float4*)out)[v4] = r;
    }
}

// ---------------- launch ----------------
extern "C" void kernel_launch(void* const* d_in, const int* in_sizes, int n_in,
                              void* d_out, int out_size) {
    const float* x       = (const float*)d_in[0];
    const int*   ei      = (const int*)d_in[1];
    const float* W       = (const float*)d_in[2];
    const float* att_src = (const float*)d_in[3];
    const float* att_dst = (const float*)d_in[4];
    const float* gamma   = (const float*)d_in[6];
    const float* beta    = (const float*)d_in[7];
    float*       out     = (float*)d_out;

    cudaFuncSetAttribute(k_gemm_hist, cudaFuncAttributeMaxDynamicSharedMemorySize, (int)SMEM_DYN);

    k_zero_deg<<<(N_NODES + 255) / 256, 256>>>();
    k_zero_stats<<<1, 128>>>();
    k_zero_ctr<<<1, 1>>>();
    k_gemm_hist<<<GEMM_BLOCKS + HIST_BLOCKS, 256, SMEM_DYN>>>(x, W, att_src, att_dst, ei);  // profiled (index 3)
    k_offsets<<<(N_NODES + 255) / 256, 256>>>();
    k_fill<<<(NEDGE + 255) / 256, 256>>>(ei);
    k_aggregate<<<(N_NODES + 7) / 8, 256>>>();
    k_final<<<(N_NODES * 32 + 255) / 256, 256>>>(gamma, beta, out);
}